// round 5
// baseline (speedup 1.0000x reference)
#include <cuda_runtime.h>
#include <cuda_bf16.h>

#define D_DIM    512
#define T_DIM    512
#define NTOK     1024
#define NTHREADS 256

// Scratch (no allocations allowed): per-token sum of squares + final scalar.
__device__ double g_tokss[NTOK];
__device__ float  g_scalar;

// Deterministic block-wide fp64 sum (shuffle tree + smem across 8 warps).
__device__ __forceinline__ double block_reduce_d(double v, double* sbuf) {
    __syncthreads();  // protect sbuf reuse across consecutive reductions
    int lane = threadIdx.x & 31, w = threadIdx.x >> 5;
#pragma unroll
    for (int o = 16; o; o >>= 1) v += __shfl_down_sync(0xffffffffu, v, o);
    if (lane == 0) sbuf[w] = v;
    __syncthreads();
    if (w == 0) {
        double x = (lane < (NTHREADS / 32)) ? sbuf[lane] : 0.0;
#pragma unroll
        for (int o = 16; o; o >>= 1) x += __shfl_down_sync(0xffffffffu, x, o);
        if (lane == 0) sbuf[0] = x;
    }
    __syncthreads();
    return sbuf[0];
}

// Accurate sincos of an fp32 angle (args up to ~2.6e4). fp64 Cody-Waite
// reduction + fp64 Taylor polys: matches a correctly-rounded libm cosf/sinf
// within ~1 ulp, and is immune to --use_fast_math rewrites of sincosf.
__device__ __forceinline__ void sincos_acc(float ang, float* s_out, float* c_out) {
    double a  = (double)ang;
    double kd = rint(a * 6.36619772367581382433e-01);              // 2/pi
    double r  = fma(-kd, 1.57079632679489661923e+00, a);           // pi/2 hi
    r         = fma(-kd, 6.12323399573676603587e-17, r);           // pi/2 lo
    double z  = r * r;

    double sp = -2.50521083854417187751e-08;                       // -1/11!
    sp = fma(sp, z,  2.75573192239858906526e-06);                  //  1/9!
    sp = fma(sp, z, -1.98412698412698412699e-04);                  // -1/7!
    sp = fma(sp, z,  8.33333333333333321769e-03);                  //  1/5!
    sp = fma(sp, z, -1.66666666666666666667e-01);                  // -1/3!
    double sinr = fma(r * z, sp, r);

    double cp =  2.08767569878680989792e-09;                       //  1/12!
    cp = fma(cp, z, -2.75573192239858906526e-07);                  // -1/10!
    cp = fma(cp, z,  2.48015873015873015873e-05);                  //  1/8!
    cp = fma(cp, z, -1.38888888888888888889e-03);                  // -1/6!
    cp = fma(cp, z,  4.16666666666666666667e-02);                  //  1/4!
    cp = fma(cp, z, -5.00000000000000000000e-01);                  // -1/2
    double cosr = fma(cp, z, 1.0);

    int q = ((int)kd) & 3;
    double sv, cv;
    if      (q == 0) { sv =  sinr; cv =  cosr; }
    else if (q == 1) { sv =  cosr; cv = -sinr; }
    else if (q == 2) { sv = -sinr; cv = -cosr; }
    else             { sv = -cosr; cv =  sinr; }
    *s_out = (float)sv;
    *c_out = (float)cv;
}

// Golay (24,12) generator bit, closed form of _initialize_golay_code:
// G[k,l]: l<12 -> (l==k); l in [12,23) -> (k+(l-12))%2; l==23 -> k%2.
__device__ __forceinline__ int golay_bit(int k, int l) {
    return (l < 12) ? (l == k) : ((l < 23) ? ((k + (l - 12)) & 1) : (k & 1));
}

__global__ __launch_bounds__(NTHREADS)
void token_kernel(const int*   __restrict__ token_ids,
                  const float* __restrict__ resonances,
                  const float* __restrict__ emb_scales,
                  const float* __restrict__ emb_shifts,
                  const float* __restrict__ emb_norm,
                  const float* __restrict__ W_enc,   // [D,24] row-major
                  const float* __restrict__ b_enc,   // [24]
                  const float* __restrict__ W_dec,   // [24,D] row-major
                  const float* __restrict__ b_dec,   // [D]
                  const float* __restrict__ ecc_p,
                  const float* __restrict__ ep_p,
                  float*       __restrict__ out)
{
    __shared__ float  s_emb[D_DIM];
    __shared__ double s_red[32];
    __shared__ float  s_proj[24];
    __shared__ float  s_corr[24];
    __shared__ float  s_sc[2];

    const int bt  = blockIdx.x;
    const int tid = threadIdx.x;
    const float ecc = ecc_p[0];
    const float ep  = ep_p[0];
    const float en  = emb_norm[0];

    // ---- embedding: angle = resonances[d] * (token_value + pos) ----
    const int   t    = bt & (T_DIM - 1);
    const float tv   = __fdiv_rn((float)(token_ids[bt] % 1000000), 1000000.0f);
    const float base = __fadd_rn(tv, (float)t);

    double lss = 0.0;
    for (int d = tid; d < D_DIM; d += NTHREADS) {
        float ang = __fmul_rn(resonances[d], base);
        float s, c;
        sincos_acc(ang, &s, &c);
        // comp = c*(1+s) + s*s (explicit rounding, no surprise FMA contraction)
        float comp = __fadd_rn(__fmul_rn(c, __fadd_rn(1.0f, s)), __fmul_rn(s, s));
        float e0   = __fadd_rn(__fmul_rn(comp, emb_scales[d]), emb_shifts[d]);
        s_emb[d] = e0;
        lss = fma((double)e0, (double)e0, lss);
    }
    double ssd = block_reduce_d(lss, s_red);
    float  tn  = (float)sqrt(ssd);

    // normalize token embedding: emb = emb * emb_norm / tok_norm
    double lss2 = 0.0;
    for (int d = tid; d < D_DIM; d += NTHREADS) {
        float e = s_emb[d];
        if (tn > 0.0f) e = __fdiv_rn(__fmul_rn(e, en), tn);
        s_emb[d] = e;
        lss2 = fma((double)e, (double)e, lss2);
    }
    const float e_in = (float)sqrt(block_reduce_d(lss2, s_red));

    // ---- proj = emb @ W_enc + b_enc : 8 warps x 3 columns, fp64 accum ----
    {
        int w = tid >> 5, lane = tid & 31;
        int c0 = w * 3;
        double p0 = 0.0, p1 = 0.0, p2 = 0.0;
        for (int d = lane; d < D_DIM; d += 32) {
            double e = (double)s_emb[d];
            const float* wr = W_enc + d * 24 + c0;
            p0 = fma(e, (double)wr[0], p0);
            p1 = fma(e, (double)wr[1], p1);
            p2 = fma(e, (double)wr[2], p2);
        }
#pragma unroll
        for (int o = 16; o; o >>= 1) {
            p0 += __shfl_down_sync(0xffffffffu, p0, o);
            p1 += __shfl_down_sync(0xffffffffu, p1, o);
            p2 += __shfl_down_sync(0xffffffffu, p2, o);
        }
        if (lane == 0) {
            s_proj[c0]     = __fadd_rn((float)p0, b_enc[c0]);
            s_proj[c0 + 1] = __fadd_rn((float)p1, b_enc[c0 + 1]);
            s_proj[c0 + 2] = __fadd_rn((float)p2, b_enc[c0 + 2]);
        }
    }
    __syncthreads();

    // ---- Golay encode + quantize + renorm + decode + threshold (scalar) ----
    if (tid == 0) {
        float latt[12];
        double eo = 0.0;
#pragma unroll
        for (int k = 0; k < 12; k++) {
            float g = 0.0f;
#pragma unroll
            for (int l = 0; l < 24; l++)
                if (golay_bit(k, l)) g = __fadd_rn(g, s_proj[l]);
            // latt = round(g/ecc)*ecc ; jnp.round = half-to-even -> rintf
            float lv = __fmul_rn(rintf(__fdiv_rn(g, ecc)), ecc);
            latt[k] = lv;
            eo = fma((double)lv, (double)lv, eo);
        }
        float e_out = (float)sqrt(eo);
        float r1 = __fdiv_rn(e_in, __fadd_rn(e_out, 1e-8f));
        double ei2 = 0.0;
#pragma unroll
        for (int k = 0; k < 12; k++) {
            float lv = __fmul_rn(__fmul_rn(latt[k], r1), ep);
            latt[k] = lv;
            ei2 = fma((double)lv, (double)lv, ei2);
        }
        s_sc[0] = (float)sqrt(ei2);   // e_in2
#pragma unroll
        for (int l = 0; l < 24; l++) {
            float g = 0.0f;
#pragma unroll
            for (int k = 0; k < 12; k++)
                if (golay_bit(k, l)) g = __fadd_rn(g, latt[k]);
            s_corr[l] = (fabsf(g) > ecc) ? g : 0.0f;
        }
    }
    __syncthreads();

    // ---- res = corrected @ W_dec + b_dec, then per-token renorm ----
    double lr = 0.0;
    for (int d = tid; d < D_DIM; d += NTHREADS) {
        float acc = 0.0f;
#pragma unroll
        for (int l = 0; l < 24; l++)
            acc = __fadd_rn(acc, __fmul_rn(s_corr[l], W_dec[l * D_DIM + d]));
        acc = __fadd_rn(acc, b_dec[d]);
        s_emb[d] = acc;   // reuse smem (all prior readers passed a barrier)
        lr = fma((double)acc, (double)acc, lr);
    }
    float e_out2 = (float)sqrt(block_reduce_d(lr, s_red));
    float r2 = __fdiv_rn(s_sc[0], __fadd_rn(e_out2, 1e-8f));

    double lf = 0.0;
    for (int d = tid; d < D_DIM; d += NTHREADS) {
        float v = __fmul_rn(__fmul_rn(s_emb[d], r2), ep);
        out[bt * D_DIM + d] = v;
        lf = fma((double)v, (double)v, lf);
    }
    double tss = block_reduce_d(lf, s_red);
    if (tid == 0) g_tokss[bt] = tss;
}

// NOTE: _fractal_dimension cancels analytically:
//   fd >= 1 (clip), out_energy = |fd| = fd  =>  returned fd vector equals
//   frac_norm * ||res||_F. So output = res * frac_norm * ||res||_F.
__global__ __launch_bounds__(NTHREADS)
void finalize_kernel(const float* __restrict__ frac_norm) {
    __shared__ double s_red[32];
    double v = 0.0;
    for (int i = threadIdx.x; i < NTOK; i += NTHREADS) v += g_tokss[i];
    double tot = block_reduce_d(v, s_red);
    if (threadIdx.x == 0)
        g_scalar = __fmul_rn(frac_norm[0], (float)sqrt(tot));
}

__global__ void scale_kernel(float* __restrict__ out, int n) {
    int i = blockIdx.x * blockDim.x + threadIdx.x;
    if (i < n) out[i] = __fmul_rn(out[i], g_scalar);
}

extern "C" void kernel_launch(void* const* d_in, const int* in_sizes, int n_in,
                              void* d_out, int out_size) {
    const int*   token_ids  = (const int*)  d_in[0];
    const float* resonances = (const float*)d_in[1];
    const float* emb_scales = (const float*)d_in[2];
    const float* emb_shifts = (const float*)d_in[3];
    const float* emb_norm   = (const float*)d_in[4];
    // d_in[5] scale_weights, d_in[6] fractal_bias: provably unused (fd cancels)
    const float* frac_norm  = (const float*)d_in[7];
    const float* W_enc      = (const float*)d_in[8];
    const float* b_enc      = (const float*)d_in[9];
    const float* W_dec      = (const float*)d_in[10];
    const float* b_dec      = (const float*)d_in[11];
    const float* ecc        = (const float*)d_in[12];
    const float* ep         = (const float*)d_in[13];
    float* out = (float*)d_out;

    token_kernel<<<NTOK, NTHREADS>>>(token_ids, resonances, emb_scales, emb_shifts,
                                     emb_norm, W_enc, b_enc, W_dec, b_dec,
                                     ecc, ep, out);
    finalize_kernel<<<1, NTHREADS>>>(frac_norm);
    const int n = NTOK * D_DIM;
    scale_kernel<<<(n + NTHREADS - 1) / NTHREADS, NTHREADS>>>(out, n);
}

// round 7
// speedup vs baseline: 6.6003x; 6.6003x over previous
#include <cuda_runtime.h>
#include <cuda_bf16.h>

#define D_DIM    512
#define T_DIM    512
#define NTOK     1024
#define NTHREADS 256
#define NWARPS   (NTHREADS / 32)

// Scratch (no allocations allowed): per-token sum of squares + final scalar.
__device__ float g_tokss[NTOK];
__device__ float g_scalar;

// Deterministic block-wide fp32 sum (shuffle tree + smem across 8 warps).
__device__ __forceinline__ float block_reduce_f(float v, float* sbuf) {
    __syncthreads();  // protect sbuf reuse across consecutive reductions
    int lane = threadIdx.x & 31, w = threadIdx.x >> 5;
#pragma unroll
    for (int o = 16; o; o >>= 1) v += __shfl_down_sync(0xffffffffu, v, o);
    if (lane == 0) sbuf[w] = v;
    __syncthreads();
    if (w == 0) {
        float x = (lane < NWARPS) ? sbuf[lane] : 0.0f;
#pragma unroll
        for (int o = 16; o; o >>= 1) x += __shfl_down_sync(0xffffffffu, x, o);
        if (lane == 0) sbuf[0] = x;
    }
    __syncthreads();
    return sbuf[0];
}

// fp32 sincos, args in [0, ~2.6e4]. k = a*2/pi fits in 15 bits (a < 25600 ->
// k <= 16298 < 2^14), so the 2-term Cody-Waite with exact-product fmaf gives
// |r_err| <~ 1.2e-7:  pi/2 = C1f + C2,  C1f = float(pi/2),
// C2 = pi/2 - C1f = -4.37113900e-8 (its own float residual is 1.8e-15*k ~ 3e-11).
// A wrong-by-one k from the fp32 k-estimate only pushes |r| to <= 0.79, which
// the polynomials cover. Immune to --use_fast_math (explicit fmaf/rintf).
__device__ __forceinline__ void sincos_fast(float a, float* s_out, float* c_out) {
    float kf = rintf(__fmul_rn(a, 0.63661977236758138f));   // 2/pi
    int   q  = (int)kf;
    float r  = fmaf(kf, -1.57079632679489662f, a);          // -> -float(pi/2)
    r        = fmaf(kf,  4.37113900018624283e-08f, r);      // -> -(pi/2 - C1f)
    float z  = __fmul_rn(r, r);                              // z <= 0.63

    // sin(r): r + r^3*(S); truncation r^11/11! < 2e-9 at |r|=0.79
    float sp = 2.75573192e-06f;                             //  1/9!
    sp = fmaf(sp, z, -1.98412698e-04f);                     // -1/7!
    sp = fmaf(sp, z,  8.33333333e-03f);                     //  1/5!
    sp = fmaf(sp, z, -1.66666667e-01f);                     // -1/3!
    float sinr = fmaf(__fmul_rn(r, z), sp, r);

    // cos(r): truncation r^12/12! < 2e-10
    float cp = -2.75573192e-07f;                            // -1/10!
    cp = fmaf(cp, z,  2.48015873e-05f);                     //  1/8!
    cp = fmaf(cp, z, -1.38888889e-03f);                     // -1/6!
    cp = fmaf(cp, z,  4.16666667e-02f);                     //  1/4!
    cp = fmaf(cp, z, -0.5f);
    float cosr = fmaf(cp, z, 1.0f);

    q &= 3;
    float sv, cv;
    if      (q == 0) { sv =  sinr; cv =  cosr; }
    else if (q == 1) { sv =  cosr; cv = -sinr; }
    else if (q == 2) { sv = -sinr; cv = -cosr; }
    else             { sv = -cosr; cv =  sinr; }
    *s_out = sv;
    *c_out = cv;
}

// Golay (24,12) generator bit, closed form of _initialize_golay_code:
// G[k,l]: l<12 -> (l==k); l in [12,23) -> (k+(l-12))%2; l==23 -> k%2.
__device__ __forceinline__ int golay_bit(int k, int l) {
    return (l < 12) ? (l == k) : ((l < 23) ? ((k + (l - 12)) & 1) : (k & 1));
}

__global__ __launch_bounds__(NTHREADS)
void token_kernel(const int*   __restrict__ token_ids,
                  const float* __restrict__ resonances,
                  const float* __restrict__ emb_scales,
                  const float* __restrict__ emb_shifts,
                  const float* __restrict__ emb_norm,
                  const float* __restrict__ W_enc,   // [D,24] row-major
                  const float* __restrict__ b_enc,   // [24]
                  const float* __restrict__ W_dec,   // [24,D] row-major
                  const float* __restrict__ b_dec,   // [D]
                  const float* __restrict__ ecc_p,
                  const float* __restrict__ ep_p,
                  float*       __restrict__ out)
{
    __shared__ float s_emb[D_DIM];
    __shared__ float s_red[32];
    __shared__ float s_part[NWARPS * 24];
    __shared__ float s_proj[24];
    __shared__ float s_latt[12];
    __shared__ float s_corr[24];
    __shared__ float s_sc[1];

    const int bt   = blockIdx.x;
    const int tid  = threadIdx.x;
    const int lane = tid & 31;
    const int w    = tid >> 5;
    const float ecc = ecc_p[0];
    const float ep  = ep_p[0];
    const float en  = emb_norm[0];

    // ---- embedding: angle = resonances[d] * (token_value + pos) ----
    const int   t    = bt & (T_DIM - 1);
    const float tv   = __fdiv_rn((float)(token_ids[bt] % 1000000), 1000000.0f);
    const float base = __fadd_rn(tv, (float)t);

    float e0[2];
    float ss = 0.0f;
#pragma unroll
    for (int i = 0; i < 2; i++) {
        int d = tid + i * NTHREADS;
        float ang = __fmul_rn(resonances[d], base);
        float s, c;
        sincos_fast(ang, &s, &c);
        // comp = c*(1+s) + s*s (explicit rounding)
        float comp = __fadd_rn(__fmul_rn(c, __fadd_rn(1.0f, s)), __fmul_rn(s, s));
        float e    = __fadd_rn(__fmul_rn(comp, emb_scales[d]), emb_shifts[d]);
        e0[i] = e;
        ss = fmaf(e, e, ss);
    }
    float tn = __fsqrt_rn(block_reduce_f(ss, s_red));

    // normalize: emb *= en/tn   (||emb|| == en to ~1e-7, so e_in := en below)
    float rcp = (tn > 0.0f) ? __fdiv_rn(en, tn) : 1.0f;
#pragma unroll
    for (int i = 0; i < 2; i++) {
        s_emb[tid + i * NTHREADS] = __fmul_rn(e0[i], rcp);
    }
    __syncthreads();

    // ---- encode: proj = emb @ W_enc + b_enc ----
    // Each warp owns a contiguous 64-row slab of W_enc; 24 lanes read one
    // 96-byte row coalescedly, lane c accumulates column c's partial.
    {
        float pw = 0.0f;
        if (lane < 24) {
            const int d0 = w * (D_DIM / NWARPS);
            const float* wp = W_enc + d0 * 24 + lane;
#pragma unroll 4
            for (int j = 0; j < D_DIM / NWARPS; j++) {
                pw = fmaf(s_emb[d0 + j], wp[j * 24], pw);
            }
            s_part[w * 24 + lane] = pw;
        }
    }
    __syncthreads();

    // ---- Golay section on warp 0 (lanes parallel, shuffle reductions) ----
    if (w == 0) {
        // combine warp partials + bias
        if (lane < 24) {
            float p = s_part[lane];
#pragma unroll
            for (int ww = 1; ww < NWARPS; ww++)
                p = __fadd_rn(p, s_part[ww * 24 + lane]);
            s_proj[lane] = __fadd_rn(p, b_enc[lane]);
        }
        __syncwarp();

        // encode row k = lane (<12), ascending-l add order
        float lv = 0.0f;
        if (lane < 12) {
            float g = 0.0f;
#pragma unroll
            for (int l = 0; l < 24; l++) {
                float bterm = golay_bit(lane, l) ? s_proj[l] : 0.0f;  // +0 exact
                g = __fadd_rn(g, bterm);
            }
            // latt = round(g/ecc)*ecc ; jnp.round = half-to-even -> rintf
            lv = __fmul_rn(rintf(__fdiv_rn(g, ecc)), ecc);
        }
        float eo = __fmul_rn(lv, lv);
#pragma unroll
        for (int o = 16; o; o >>= 1) eo += __shfl_xor_sync(0xffffffffu, eo, o);
        float e_out = __fsqrt_rn(eo);
        float r1 = __fdiv_rn(en, __fadd_rn(e_out, 1e-8f));  // e_in := en
        float lvs = __fmul_rn(__fmul_rn(lv, r1), ep);

        float ei2 = __fmul_rn(lvs, lvs);
#pragma unroll
        for (int o = 16; o; o >>= 1) ei2 += __shfl_xor_sync(0xffffffffu, ei2, o);

        if (lane < 12) s_latt[lane] = lvs;
        if (lane == 0) s_sc[0] = __fsqrt_rn(ei2);           // e_in2
        __syncwarp();

        // decode column l = lane (<24), ascending-k order, then threshold
        if (lane < 24) {
            float g = 0.0f;
#pragma unroll
            for (int k = 0; k < 12; k++) {
                float bterm = golay_bit(k, lane) ? s_latt[k] : 0.0f;
                g = __fadd_rn(g, bterm);
            }
            s_corr[lane] = (fabsf(g) > ecc) ? g : 0.0f;
        }
    }
    __syncthreads();

    // ---- res = corrected @ W_dec + b_dec, renorm, write, token sumsq ----
    float cr[24];
#pragma unroll
    for (int l = 0; l < 24; l++) cr[l] = s_corr[l];

    float acc[2];
    float lr = 0.0f;
#pragma unroll
    for (int i = 0; i < 2; i++) {
        int d = tid + i * NTHREADS;
        float a = 0.0f;
#pragma unroll
        for (int l = 0; l < 24; l++)
            a = __fadd_rn(a, __fmul_rn(cr[l], W_dec[l * D_DIM + d]));
        a = __fadd_rn(a, b_dec[d]);
        acc[i] = a;
        lr = fmaf(a, a, lr);
    }
    float e_out2 = __fsqrt_rn(block_reduce_f(lr, s_red));
    float r2 = __fdiv_rn(s_sc[0], __fadd_rn(e_out2, 1e-8f));

    float lf = 0.0f;
#pragma unroll
    for (int i = 0; i < 2; i++) {
        float v = __fmul_rn(__fmul_rn(acc[i], r2), ep);
        out[bt * D_DIM + tid + i * NTHREADS] = v;
        lf = fmaf(v, v, lf);
    }
    float tss = block_reduce_f(lf, s_red);
    if (tid == 0) g_tokss[bt] = tss;
}

// NOTE: _fractal_dimension cancels analytically:
//   fd >= 1 (clip), out_energy = |fd| = fd  =>  returned fd vector equals
//   frac_norm * ||res||_F. So output = res * frac_norm * ||res||_F.
__global__ __launch_bounds__(NTHREADS)
void finalize_kernel(const float* __restrict__ frac_norm) {
    __shared__ float s_red[32];
    float v = 0.0f;
    for (int i = threadIdx.x; i < NTOK; i += NTHREADS) v += g_tokss[i];
    float tot = block_reduce_f(v, s_red);
    if (threadIdx.x == 0)
        g_scalar = __fmul_rn(frac_norm[0], __fsqrt_rn(tot));
}

__global__ void scale_kernel(float4* __restrict__ out, int n4) {
    int i = blockIdx.x * blockDim.x + threadIdx.x;
    if (i < n4) {
        float s = g_scalar;
        float4 v = out[i];
        v.x = __fmul_rn(v.x, s);
        v.y = __fmul_rn(v.y, s);
        v.z = __fmul_rn(v.z, s);
        v.w = __fmul_rn(v.w, s);
        out[i] = v;
    }
}

extern "C" void kernel_launch(void* const* d_in, const int* in_sizes, int n_in,
                              void* d_out, int out_size) {
    const int*   token_ids  = (const int*)  d_in[0];
    const float* resonances = (const float*)d_in[1];
    const float* emb_scales = (const float*)d_in[2];
    const float* emb_shifts = (const float*)d_in[3];
    const float* emb_norm   = (const float*)d_in[4];
    // d_in[5] scale_weights, d_in[6] fractal_bias: provably unused (fd cancels)
    const float* frac_norm  = (const float*)d_in[7];
    const float* W_enc      = (const float*)d_in[8];
    const float* b_enc      = (const float*)d_in[9];
    const float* W_dec      = (const float*)d_in[10];
    const float* b_dec      = (const float*)d_in[11];
    const float* ecc        = (const float*)d_in[12];
    const float* ep         = (const float*)d_in[13];
    float* out = (float*)d_out;

    token_kernel<<<NTOK, NTHREADS>>>(token_ids, resonances, emb_scales, emb_shifts,
                                     emb_norm, W_enc, b_enc, W_dec, b_dec,
                                     ecc, ep, out);
    finalize_kernel<<<1, NTHREADS>>>(frac_norm);
    const int n4 = (NTOK * D_DIM) / 4;
    scale_kernel<<<(n4 + NTHREADS - 1) / NTHREADS, NTHREADS>>>((float4*)out, n4);
}

// round 10
// speedup vs baseline: 6.6809x; 1.0122x over previous
#include <cuda_runtime.h>
#include <cuda_bf16.h>

#define D_DIM     512
#define T_MASK    511
#define NTOK      1024
#define NTHREADS  128
#define TOK_PER_BLK 4
#define NBLOCKS   (NTOK / TOK_PER_BLK)

// Device-global scratch (no allocations allowed).
__device__ float g_tokss[NTOK];
__device__ float g_scalar;

// fp32 sincos, args in [0, ~2.6e4]. k = a*2/pi fits in 15 bits, so the 2-term
// Cody-Waite with exact-product fmaf gives |r_err| <~ 1.2e-7. Immune to
// --use_fast_math (explicit fmaf/rintf).
__device__ __forceinline__ void sincos_fast(float a, float* s_out, float* c_out) {
    float kf = rintf(__fmul_rn(a, 0.63661977236758138f));   // 2/pi
    int   q  = (int)kf;
    float r  = fmaf(kf, -1.57079632679489662f, a);          // -float(pi/2)
    r        = fmaf(kf,  4.37113900018624283e-08f, r);      // -(pi/2 - C1f)
    float z  = __fmul_rn(r, r);

    float sp = 2.75573192e-06f;                             //  1/9!
    sp = fmaf(sp, z, -1.98412698e-04f);                     // -1/7!
    sp = fmaf(sp, z,  8.33333333e-03f);                     //  1/5!
    sp = fmaf(sp, z, -1.66666667e-01f);                     // -1/3!
    float sinr = fmaf(__fmul_rn(r, z), sp, r);

    float cp = -2.75573192e-07f;                            // -1/10!
    cp = fmaf(cp, z,  2.48015873e-05f);                     //  1/8!
    cp = fmaf(cp, z, -1.38888889e-03f);                     // -1/6!
    cp = fmaf(cp, z,  4.16666667e-02f);                     //  1/4!
    cp = fmaf(cp, z, -0.5f);
    float cosr = fmaf(cp, z, 1.0f);

    q &= 3;
    float sv, cv;
    if      (q == 0) { sv =  sinr; cv =  cosr; }
    else if (q == 1) { sv =  cosr; cv = -sinr; }
    else if (q == 2) { sv = -sinr; cv = -cosr; }
    else             { sv = -cosr; cv =  sinr; }
    *s_out = sv;
    *c_out = cv;
}

// One warp per token. All reductions are intra-warp shuffle butterflies; the
// only block barriers are around the two W_enc smem staging phases.
__global__ __launch_bounds__(NTHREADS)
void token_kernel(const int*   __restrict__ token_ids,
                  const float* __restrict__ resonances,
                  const float* __restrict__ emb_scales,
                  const float* __restrict__ emb_shifts,
                  const float* __restrict__ emb_norm,
                  const float* __restrict__ W_enc,   // [512,24] row-major
                  const float* __restrict__ b_enc,   // [24]
                  const float* __restrict__ W_dec,   // [24,512] row-major
                  const float* __restrict__ b_dec,   // [512]
                  const float* __restrict__ ecc_p,
                  const float* __restrict__ ep_p,
                  float*       __restrict__ out)
{
    // W_enc staged in halves of 256 rows; rows padded to 25 floats so LDS at
    // (lane+32i)*25+c hits bank (25*lane+K)%32 — bijection in lane -> no
    // conflicts. 25.6 KB static smem, 128 threads: >=2 blocks/SM.
    __shared__ float s_wenc[256 * 25];

    const int tid  = threadIdx.x;
    const int lane = tid & 31;
    const int w    = tid >> 5;
    const int bt   = blockIdx.x * TOK_PER_BLK + w;

    const float ecc = ecc_p[0];
    const float ep  = ep_p[0];
    const float en  = emb_norm[0];

    // ---- embedding: angle = resonances[d]*(token_value + pos), d = lane+32i
    const int   t    = bt & T_MASK;
    const float tv   = __fdiv_rn((float)(token_ids[bt] % 1000000), 1000000.0f);
    const float base = __fadd_rn(tv, (float)t);

    float e[16];
    float ss = 0.0f;
#pragma unroll
    for (int i = 0; i < 16; i++) {
        int d = lane + 32 * i;
        float ang = __fmul_rn(resonances[d], base);
        float s, c;
        sincos_fast(ang, &s, &c);
        float comp = __fadd_rn(__fmul_rn(c, __fadd_rn(1.0f, s)), __fmul_rn(s, s));
        float ev   = __fadd_rn(__fmul_rn(comp, emb_scales[d]), emb_shifts[d]);
        e[i] = ev;
        ss = fmaf(ev, ev, ss);
    }
#pragma unroll
    for (int o = 16; o; o >>= 1) ss += __shfl_xor_sync(0xffffffffu, ss, o);
    float tn  = __fsqrt_rn(ss);
    float rcp = (tn > 0.0f) ? __fdiv_rn(en, tn) : 1.0f;
#pragma unroll
    for (int i = 0; i < 16; i++) e[i] = __fmul_rn(e[i], rcp);

    // ---- encode: proj[c] = sum_d emb[d]*W_enc[d][c], via 2 smem halves ----
    float proj[24];
#pragma unroll
    for (int c = 0; c < 24; c++) proj[c] = 0.0f;

#pragma unroll
    for (int h = 0; h < 2; h++) {
        __syncthreads();   // previous half's readers done before overwrite
        // stage 256 rows x 24 floats = 1536 float4, coalesced read, padded STS
        for (int m4 = tid; m4 < 1536; m4 += NTHREADS) {
            float4 v = ((const float4*)W_enc)[h * 1536 + m4];
            int d = m4 / 6;
            int b = d * 25 + (m4 % 6) * 4;
            s_wenc[b]     = v.x;
            s_wenc[b + 1] = v.y;
            s_wenc[b + 2] = v.z;
            s_wenc[b + 3] = v.w;
        }
        __syncthreads();
#pragma unroll
        for (int i = 0; i < 8; i++) {
            float ev = e[h * 8 + i];
            const float* wr = &s_wenc[(lane + 32 * i) * 25];
#pragma unroll
            for (int c = 0; c < 24; c++) proj[c] = fmaf(ev, wr[c], proj[c]);
        }
    }
    // butterfly-reduce all 24 columns across lanes (all lanes get full sums)
#pragma unroll
    for (int c = 0; c < 24; c++) {
        float p = proj[c];
#pragma unroll
        for (int o = 16; o; o >>= 1) p += __shfl_xor_sync(0xffffffffu, p, o);
        proj[c] = __fadd_rn(p, b_enc[c]);
    }

    // ---- Golay encode row k=lane(<12): quantize round(g/ecc)*ecc ----
    // golay_bit(k,l): l<12 -> l==k; l in [12,23) -> (k+l-12)%2; l==23 -> k%2.
    float lv = 0.0f;
    if (lane < 12) {
        float g = 0.0f;
#pragma unroll
        for (int l = 0; l < 24; l++) {
            bool bit = (l < 12) ? (l == lane)
                     : ((l < 23) ? (((lane + l - 12) & 1) != 0)
                                 : ((lane & 1) != 0));
            if (bit) g = __fadd_rn(g, proj[l]);
        }
        lv = __fmul_rn(rintf(__fdiv_rn(g, ecc)), ecc);   // half-to-even
    }
    float eo = __fmul_rn(lv, lv);
#pragma unroll
    for (int o = 16; o; o >>= 1) eo += __shfl_xor_sync(0xffffffffu, eo, o);
    float e_out = __fsqrt_rn(eo);
    float r1  = __fdiv_rn(en, __fadd_rn(e_out, 1e-8f));   // e_in := emb_norm
    float lvs = __fmul_rn(__fmul_rn(lv, r1), ep);

    float ei2 = __fmul_rn(lvs, lvs);
#pragma unroll
    for (int o = 16; o; o >>= 1) ei2 += __shfl_xor_sync(0xffffffffu, ei2, o);
    float e_in2 = __fsqrt_rn(ei2);

    // ---- Golay decode col l=lane(<24) + threshold, broadcast cr[24] ----
    float gd = 0.0f;
#pragma unroll
    for (int k = 0; k < 12; k++) {
        float lk = __shfl_sync(0xffffffffu, lvs, k);
        bool bit = (lane < 12) ? (lane == k)
                 : ((lane < 23) ? (((k + lane - 12) & 1) != 0)
                                : ((k & 1) != 0));
        if (bit) gd = __fadd_rn(gd, lk);
    }
    float corrv = (fabsf(gd) > ecc) ? gd : 0.0f;
    float cr[24];
#pragma unroll
    for (int l = 0; l < 24; l++) cr[l] = __shfl_sync(0xffffffffu, corrv, l);

    // ---- res = corrected @ W_dec + b_dec (lane owns dim-pairs, LDG.64) ----
    float v0[8], v1[8];
    float lr = 0.0f;
#pragma unroll
    for (int i = 0; i < 8; i++) {
        int d0 = 2 * lane + 64 * i;
        float a0 = 0.0f, a1 = 0.0f;
#pragma unroll
        for (int l = 0; l < 24; l++) {
            float2 w2 = *(const float2*)(W_dec + l * D_DIM + d0);
            a0 = fmaf(cr[l], w2.x, a0);
            a1 = fmaf(cr[l], w2.y, a1);
        }
        float2 b2 = *(const float2*)(b_dec + d0);
        a0 = __fadd_rn(a0, b2.x);
        a1 = __fadd_rn(a1, b2.y);
        v0[i] = a0; v1[i] = a1;
        lr = fmaf(a0, a0, fmaf(a1, a1, lr));
    }
#pragma unroll
    for (int o = 16; o; o >>= 1) lr += __shfl_xor_sync(0xffffffffu, lr, o);
    float e_out2 = __fsqrt_rn(lr);
    float r2ep = __fmul_rn(__fdiv_rn(e_in2, __fadd_rn(e_out2, 1e-8f)), ep);

    // write unscaled res; global scalar applied by scale_kernel
    float lf = 0.0f;
#pragma unroll
    for (int i = 0; i < 8; i++) {
        float a0 = __fmul_rn(v0[i], r2ep);
        float a1 = __fmul_rn(v1[i], r2ep);
        float2 o2; o2.x = a0; o2.y = a1;
        *(float2*)(out + bt * D_DIM + 2 * lane + 64 * i) = o2;
        lf = fmaf(a0, a0, fmaf(a1, a1, lf));
    }
#pragma unroll
    for (int o = 16; o; o >>= 1) lf += __shfl_xor_sync(0xffffffffu, lf, o);
    if (lane == 0) g_tokss[bt] = lf;
}

// NOTE: _fractal_dimension cancels analytically: fd >= 1 (clip), out_energy =
// |fd| = fd => returned fd equals frac_norm * ||res||_F.
// So output = res * frac_norm * ||res||_F.
__global__ __launch_bounds__(256)
void finalize_kernel(const float* __restrict__ frac_norm) {
    __shared__ float sbuf[8];
    int lane = threadIdx.x & 31, w = threadIdx.x >> 5;
    float v = 0.0f;
#pragma unroll
    for (int k = 0; k < NTOK / 256; k++)
        v = __fadd_rn(v, g_tokss[threadIdx.x + k * 256]);
#pragma unroll
    for (int o = 16; o; o >>= 1) v += __shfl_xor_sync(0xffffffffu, v, o);
    if (lane == 0) sbuf[w] = v;
    __syncthreads();
    if (threadIdx.x == 0) {
        float tot = 0.0f;
#pragma unroll
        for (int i = 0; i < 8; i++) tot = __fadd_rn(tot, sbuf[i]);
        g_scalar = __fmul_rn(frac_norm[0], __fsqrt_rn(tot));
    }
}

__global__ void scale_kernel(float4* __restrict__ out, int n4) {
    int i = blockIdx.x * blockDim.x + threadIdx.x;
    if (i < n4) {
        float s = g_scalar;
        float4 v = out[i];
        v.x = __fmul_rn(v.x, s);
        v.y = __fmul_rn(v.y, s);
        v.z = __fmul_rn(v.z, s);
        v.w = __fmul_rn(v.w, s);
        out[i] = v;
    }
}

extern "C" void kernel_launch(void* const* d_in, const int* in_sizes, int n_in,
                              void* d_out, int out_size) {
    const int*   token_ids  = (const int*)  d_in[0];
    const float* resonances = (const float*)d_in[1];
    const float* emb_scales = (const float*)d_in[2];
    const float* emb_shifts = (const float*)d_in[3];
    const float* emb_norm   = (const float*)d_in[4];
    // d_in[5] scale_weights, d_in[6] fractal_bias: provably unused (fd cancels)
    const float* frac_norm  = (const float*)d_in[7];
    const float* W_enc      = (const float*)d_in[8];
    const float* b_enc      = (const float*)d_in[9];
    const float* W_dec      = (const float*)d_in[10];
    const float* b_dec      = (const float*)d_in[11];
    const float* ecc        = (const float*)d_in[12];
    const float* ep         = (const float*)d_in[13];
    float* out = (float*)d_out;

    token_kernel<<<NBLOCKS, NTHREADS>>>(token_ids, resonances, emb_scales,
                                        emb_shifts, emb_norm, W_enc, b_enc,
                                        W_dec, b_dec, ecc, ep, out);
    finalize_kernel<<<1, 256>>>(frac_norm);
    const int n4 = (NTOK * D_DIM) / 4;
    scale_kernel<<<(n4 + 255) / 256, 256>>>((float4*)out, n4);
}